// round 1
// baseline (speedup 1.0000x reference)
#include <cuda_runtime.h>
#include <math.h>

#define B_  32
#define M_  10
#define MN  1010
#define D_  128
#define NODES_TOT (B_*MN*D_)   // 4,136,960

// ------------------------- device scratch -------------------------
__device__ __align__(16) float g_pe_proj[M_*D_];   // (i,k): pe[i] @ W_posproj^T
__device__ __align__(16) float g_vpref[D_];        // Wp @ W_pref
__device__ __align__(16) float g_WnWcT[5*D_];      // (c,d): (Wn @ W_clients)^T
__device__ __align__(16) float g_WnWaT[4*D_];      // (c,d): (Wn @ W_agents)^T
__device__ __align__(16) float g_WcT[5*D_];        // (c,d): W_clients^T
__device__ __align__(16) float g_WaT[4*D_];        // (c,d): W_agents^T
__device__ __align__(16) float g_B1[D_*2];         // (e,c): Wda1 @ W_depot
__device__ __align__(16) float g_B2[D_*4];         // (e,c): Wda2 @ W_agents
__device__ __align__(16) float g_PP[D_*M_];        // (e,i): Wda1 @ pe_proj^T
__device__ __align__(16) float g_A1T[2*D_];        // (c,d)
__device__ __align__(16) float g_A2T[4*D_];        // (c,d)
__device__ __align__(16) float g_P1[M_*D_];        // (i,d)  (alpha folded in)
__device__ __align__(16) float g_PD[B_*M_*D_];     // (b,i,d): depot_agents @ Wd^T

__device__ __forceinline__ float warp_sum(float v) {
    #pragma unroll
    for (int o = 16; o > 0; o >>= 1) v += __shfl_down_sync(0xffffffffu, v, o);
    return v;
}

// ------------------------- stage A: small fused matrices -------------------------
__global__ void pk_a(const float* __restrict__ Wpos, const float* __restrict__ Wfin,
                     const float* __restrict__ Wprf, const float* __restrict__ Wcli,
                     const float* __restrict__ Wag) {
    int blk = blockIdx.x;
    int t = threadIdx.x, w = t >> 5, lane = t & 31;

    if (blk < M_) {
        // pe_proj row i = blk : sum_k pe[i][k] * Wpos[d][k]
        __shared__ float pe[D_];
        if (t < D_) {
            int j = t >> 1;
            float c = -logf(10000.0f) / (float)D_;
            float div = expf((float)(2 * j) * c);
            float ang = (float)blk * div;
            pe[t] = (t & 1) ? cosf(ang) : sinf(ang);
        }
        __syncthreads();
        float p0 = pe[lane*4+0], p1 = pe[lane*4+1], p2 = pe[lane*4+2], p3 = pe[lane*4+3];
        for (int d = w; d < D_; d += 4) {
            float4 wv = *(const float4*)&Wpos[d*D_ + lane*4];
            float s = warp_sum(wv.x*p0 + wv.y*p1 + wv.z*p2 + wv.w*p3);
            if (lane == 0) g_pe_proj[blk*D_ + d] = s;
        }
    } else if (blk == M_) {
        // v_pref[d] = sum_k Wp[d][k] * W_pref[k]
        float4 pv = *(const float4*)&Wprf[lane*4];
        for (int d = w; d < D_; d += 4) {
            float4 wv = *(const float4*)&Wfin[d*384 + 128 + lane*4];
            float s = warp_sum(wv.x*pv.x + wv.y*pv.y + wv.z*pv.z + wv.w*pv.w);
            if (lane == 0) g_vpref[d] = s;
        }
    } else if (blk == M_+1) {
        // WnWcT[c][d] = sum_k Wn[d][k] * Wcli[k][c]
        for (int d = w; d < D_; d += 4) {
            float4 wn = *(const float4*)&Wfin[d*384 + lane*4];
            int k0 = lane * 4;
            float acc[5];
            #pragma unroll
            for (int c = 0; c < 5; c++) {
                acc[c] = wn.x*Wcli[(k0+0)*5+c] + wn.y*Wcli[(k0+1)*5+c]
                       + wn.z*Wcli[(k0+2)*5+c] + wn.w*Wcli[(k0+3)*5+c];
            }
            #pragma unroll
            for (int c = 0; c < 5; c++) {
                float s = warp_sum(acc[c]);
                if (lane == 0) g_WnWcT[c*D_ + d] = s;
            }
        }
    } else if (blk == M_+2) {
        // WnWaT[c][d] = sum_k Wn[d][k] * Wag[k][c]
        for (int d = w; d < D_; d += 4) {
            float4 wn = *(const float4*)&Wfin[d*384 + lane*4];
            int k0 = lane * 4;
            float acc[4];
            #pragma unroll
            for (int c = 0; c < 4; c++) {
                acc[c] = wn.x*Wag[(k0+0)*4+c] + wn.y*Wag[(k0+1)*4+c]
                       + wn.z*Wag[(k0+2)*4+c] + wn.w*Wag[(k0+3)*4+c];
            }
            #pragma unroll
            for (int c = 0; c < 4; c++) {
                float s = warp_sum(acc[c]);
                if (lane == 0) g_WnWaT[c*D_ + d] = s;
            }
        }
    } else {
        // transposes of the tiny weight matrices
        for (int idx = t; idx < 5*D_; idx += blockDim.x) {
            int c = idx / D_, d = idx % D_;
            g_WcT[idx] = Wcli[d*5 + c];
        }
        for (int idx = t; idx < 4*D_; idx += blockDim.x) {
            int c = idx / D_, d = idx % D_;
            g_WaT[idx] = Wag[d*4 + c];
        }
    }
}

// ------------------------- stage B: Wda-row contractions -------------------------
__global__ void pk_b(const float* __restrict__ Wda, const float* __restrict__ Wdep,
                     const float* __restrict__ Wag) {
    int w = threadIdx.x >> 5, lane = threadIdx.x & 31;
    int e = blockIdx.x * 4 + w;          // 0..127
    int k0 = lane * 4;
    float4 a  = *(const float4*)&Wda[e*256 + k0];         // first half (depot part)
    float4 bq = *(const float4*)&Wda[e*256 + 128 + k0];   // second half (agents part)

    float acc[16];
    #pragma unroll
    for (int c = 0; c < 2; c++) {
        acc[c] = a.x*Wdep[(k0+0)*2+c] + a.y*Wdep[(k0+1)*2+c]
               + a.z*Wdep[(k0+2)*2+c] + a.w*Wdep[(k0+3)*2+c];
    }
    #pragma unroll
    for (int c = 0; c < 4; c++) {
        acc[2+c] = bq.x*Wag[(k0+0)*4+c] + bq.y*Wag[(k0+1)*4+c]
                 + bq.z*Wag[(k0+2)*4+c] + bq.w*Wag[(k0+3)*4+c];
    }
    #pragma unroll
    for (int i = 0; i < M_; i++) {
        acc[6+i] = a.x*g_pe_proj[i*D_+k0+0] + a.y*g_pe_proj[i*D_+k0+1]
                 + a.z*g_pe_proj[i*D_+k0+2] + a.w*g_pe_proj[i*D_+k0+3];
    }
    #pragma unroll
    for (int r = 0; r < 16; r++) {
        float s = warp_sum(acc[r]);
        if (lane == 0) {
            if (r < 2)      g_B1[e*2 + r] = s;
            else if (r < 6) g_B2[e*4 + (r-2)] = s;
            else            g_PP[e*M_ + (r-6)] = s;
        }
    }
}

// ------------------------- stage C: contract with Wd -------------------------
__global__ void pk_c(const float* __restrict__ Wfin, const float* __restrict__ alp) {
    int w = threadIdx.x >> 5, lane = threadIdx.x & 31;
    int d = blockIdx.x * 4 + w;          // 0..127
    int e0 = lane * 4;
    float4 wd = *(const float4*)&Wfin[d*384 + 256 + e0];  // Wd[d][e0..e0+3]
    float alpha = alp[0];

    float acc[16];
    #pragma unroll
    for (int c = 0; c < 2; c++) {
        acc[c] = wd.x*g_B1[(e0+0)*2+c] + wd.y*g_B1[(e0+1)*2+c]
               + wd.z*g_B1[(e0+2)*2+c] + wd.w*g_B1[(e0+3)*2+c];
    }
    #pragma unroll
    for (int c = 0; c < 4; c++) {
        acc[2+c] = wd.x*g_B2[(e0+0)*4+c] + wd.y*g_B2[(e0+1)*4+c]
                 + wd.z*g_B2[(e0+2)*4+c] + wd.w*g_B2[(e0+3)*4+c];
    }
    #pragma unroll
    for (int i = 0; i < M_; i++) {
        acc[6+i] = wd.x*g_PP[(e0+0)*M_+i] + wd.y*g_PP[(e0+1)*M_+i]
                 + wd.z*g_PP[(e0+2)*M_+i] + wd.w*g_PP[(e0+3)*M_+i];
    }
    #pragma unroll
    for (int r = 0; r < 16; r++) {
        float s = warp_sum(acc[r]);
        if (lane == 0) {
            if (r < 2)      g_A1T[r*D_ + d] = s;
            else if (r < 6) g_A2T[(r-2)*D_ + d] = s;
            else            g_P1[(r-6)*D_ + d] = alpha * s;
        }
    }
}

// ------------------------- stage D: per-(b,i) depot-agents projection -------------------------
__global__ void pk_d(const float* __restrict__ locs, const float* __restrict__ cap,
                     const float* __restrict__ spd) {
    int b = blockIdx.x, d = threadIdx.x;
    float a10 = g_A1T[d],      a11 = g_A1T[D_+d];
    float a20 = g_A2T[d],      a21 = g_A2T[D_+d];
    float a22 = g_A2T[2*D_+d], a23 = g_A2T[3*D_+d];
    #pragma unroll
    for (int i = 0; i < M_; i++) {
        float x = locs[(b*MN+i)*2+0], y = locs[(b*MN+i)*2+1];
        float c = cap[b*M_+i] * 0.025f;   // /40
        float s = spd[b*M_+i];            // /1
        g_PD[(b*M_+i)*D_+d] = a10*x + a11*y + g_P1[i*D_+d]
                            + a20*x + a21*y + a22*c + a23*s;
    }
}

// ------------------------- main kernel: nodes + combined (store-bound) -------------------------
__global__ void __launch_bounds__(128) mk(
        const float* __restrict__ locs, const float* __restrict__ cap,
        const float* __restrict__ spd,  const float* __restrict__ dem,
        const float* __restrict__ pref, float* __restrict__ out) {
    int b = blockIdx.y;
    int w = threadIdx.x >> 5, lane = threadIdx.x & 31;
    int j = blockIdx.x * 4 + w;
    if (j >= MN) return;
    int d0 = lane * 4;

    float4 vp = *(const float4*)&g_vpref[d0];
    float4 ce, pn;
    float x = locs[(b*MN+j)*2+0], y = locs[(b*MN+j)*2+1];

    if (j < M_) {
        float f2 = cap[b*M_+j] * 0.025f;
        float f3 = spd[b*M_+j];
        float4 w0 = *(const float4*)&g_WaT[0*D_+d0];
        float4 w1 = *(const float4*)&g_WaT[1*D_+d0];
        float4 w2 = *(const float4*)&g_WaT[2*D_+d0];
        float4 w3 = *(const float4*)&g_WaT[3*D_+d0];
        ce.x = x*w0.x + y*w1.x + f2*w2.x + f3*w3.x;
        ce.y = x*w0.y + y*w1.y + f2*w2.y + f3*w3.y;
        ce.z = x*w0.z + y*w1.z + f2*w2.z + f3*w3.z;
        ce.w = x*w0.w + y*w1.w + f2*w2.w + f3*w3.w;
        float4 n0 = *(const float4*)&g_WnWaT[0*D_+d0];
        float4 n1 = *(const float4*)&g_WnWaT[1*D_+d0];
        float4 n2 = *(const float4*)&g_WnWaT[2*D_+d0];
        float4 n3 = *(const float4*)&g_WnWaT[3*D_+d0];
        pn.x = x*n0.x + y*n1.x + f2*n2.x + f3*n3.x;
        pn.y = x*n0.y + y*n1.y + f2*n2.y + f3*n3.y;
        pn.z = x*n0.z + y*n1.z + f2*n2.z + f3*n3.z;
        pn.w = x*n0.w + y*n1.w + f2*n2.w + f3*n3.w;
    } else {
        float dx = x - locs[b*MN*2+0];
        float dy = y - locs[b*MN*2+1];
        float dist = sqrtf(dx*dx + dy*dy);
        float ang  = atan2f(dy, dx);
        float f2   = dem[b*MN+j] * 0.025f;
        float4 w0 = *(const float4*)&g_WcT[0*D_+d0];
        float4 w1 = *(const float4*)&g_WcT[1*D_+d0];
        float4 w2 = *(const float4*)&g_WcT[2*D_+d0];
        float4 w3 = *(const float4*)&g_WcT[3*D_+d0];
        float4 w4 = *(const float4*)&g_WcT[4*D_+d0];
        ce.x = x*w0.x + y*w1.x + f2*w2.x + dist*w3.x + ang*w4.x;
        ce.y = x*w0.y + y*w1.y + f2*w2.y + dist*w3.y + ang*w4.y;
        ce.z = x*w0.z + y*w1.z + f2*w2.z + dist*w3.z + ang*w4.z;
        ce.w = x*w0.w + y*w1.w + f2*w2.w + dist*w3.w + ang*w4.w;
        float4 n0 = *(const float4*)&g_WnWcT[0*D_+d0];
        float4 n1 = *(const float4*)&g_WnWcT[1*D_+d0];
        float4 n2 = *(const float4*)&g_WnWcT[2*D_+d0];
        float4 n3 = *(const float4*)&g_WnWcT[3*D_+d0];
        float4 n4 = *(const float4*)&g_WnWcT[4*D_+d0];
        pn.x = x*n0.x + y*n1.x + f2*n2.x + dist*n3.x + ang*n4.x;
        pn.y = x*n0.y + y*n1.y + f2*n2.y + dist*n3.y + ang*n4.y;
        pn.z = x*n0.z + y*n1.z + f2*n2.z + dist*n3.z + ang*n4.z;
        pn.w = x*n0.w + y*n1.w + f2*n2.w + dist*n3.w + ang*n4.w;
    }

    // output 1: nodes_embedding
    *(float4*)&out[((size_t)b*MN + j)*D_ + d0] = ce;

    // output 2: combined_embedding
    const float* pp = pref + (size_t)(b*M_)*MN + j;
    float* oc = out + NODES_TOT + ((size_t)(b*M_)*MN + (size_t)j)*D_ + d0;
    #pragma unroll
    for (int i = 0; i < M_; i++) {
        float p = pp[(size_t)i*MN];
        float4 pd = *(const float4*)&g_PD[(b*M_+i)*D_ + d0];
        float4 o;
        o.x = pn.x + p*vp.x + pd.x;
        o.y = pn.y + p*vp.y + pd.y;
        o.z = pn.z + p*vp.z + pd.z;
        o.w = pn.w + p*vp.w + pd.w;
        *(float4*)&oc[(size_t)i*MN*D_] = o;
    }
}

// ------------------------- launch -------------------------
extern "C" void kernel_launch(void* const* d_in, const int* in_sizes, int n_in,
                              void* d_out, int out_size) {
    const float* locs = (const float*)d_in[0];
    const float* cap  = (const float*)d_in[1];
    const float* spd  = (const float*)d_in[2];
    const float* dem  = (const float*)d_in[3];
    const float* pref = (const float*)d_in[4];
    // d_in[5] = action_mask (unused; shape only)
    const float* Wdep = (const float*)d_in[6];
    const float* Wpos = (const float*)d_in[7];
    const float* alp  = (const float*)d_in[8];
    const float* Wag  = (const float*)d_in[9];
    const float* Wda  = (const float*)d_in[10];
    const float* Wcli = (const float*)d_in[11];
    const float* Wprf = (const float*)d_in[12];
    const float* Wfin = (const float*)d_in[13];
    float* out = (float*)d_out;

    pk_a<<<M_ + 4, 128>>>(Wpos, Wfin, Wprf, Wcli, Wag);
    pk_b<<<32, 128>>>(Wda, Wdep, Wag);
    pk_c<<<32, 128>>>(Wfin, alp);
    pk_d<<<B_, 128>>>(locs, cap, spd);
    mk<<<dim3((MN + 3) / 4, B_), 128>>>(locs, cap, spd, dem, pref, out);
}